// round 7
// baseline (speedup 1.0000x reference)
#include <cuda_runtime.h>
#include <cuda_bf16.h>
#include <math.h>
#include <stdint.h>

#define B_   4
#define T_   2048
#define D_   1024
#define H_   16
#define HD_  64
#define M_   (B_ * T_)
#define SCALE_ 0.125f

// ---------------- scratch (device globals; no allocation allowed) ----------
__device__ __nv_bfloat16 g_xqh[(size_t)M_ * D_], g_xql[(size_t)M_ * D_];
__device__ __nv_bfloat16 g_xkh[(size_t)M_ * D_], g_xkl[(size_t)M_ * D_];
__device__ __nv_bfloat16 g_xvh[(size_t)M_ * D_], g_xvl[(size_t)M_ * D_];
__device__ __nv_bfloat16 g_wqh[(size_t)D_ * D_], g_wql[(size_t)D_ * D_];
__device__ __nv_bfloat16 g_wkh[(size_t)D_ * D_], g_wkl[(size_t)D_ * D_];
__device__ __nv_bfloat16 g_wvh[(size_t)D_ * D_], g_wvl[(size_t)D_ * D_];
__device__ __nv_bfloat16 g_woh[(size_t)D_ * D_], g_wol[(size_t)D_ * D_];
__device__ __nv_bfloat16 g_qh[(size_t)B_ * H_ * T_ * HD_], g_ql[(size_t)B_ * H_ * T_ * HD_];
__device__ __nv_bfloat16 g_kh[(size_t)B_ * H_ * T_ * HD_], g_kl[(size_t)B_ * H_ * T_ * HD_];
__device__ __nv_bfloat16 g_vh[(size_t)B_ * H_ * T_ * HD_], g_vl[(size_t)B_ * H_ * T_ * HD_];
__device__ __nv_bfloat16 g_ah[(size_t)M_ * D_], g_al[(size_t)M_ * D_];

// =========================== helpers ========================================
__device__ __forceinline__ uint32_t smem_u32(const void* p) {
    uint32_t a;
    asm("{ .reg .u64 t; cvta.to.shared.u64 t, %1; cvt.u32.u64 %0, t; }"
        : "=r"(a) : "l"(p));
    return a;
}

__device__ __forceinline__ void mma_bf16(
    float& c0, float& c1, float& c2, float& c3,
    uint32_t a0, uint32_t a1, uint32_t a2, uint32_t a3,
    uint32_t b0, uint32_t b1)
{
    asm volatile(
        "mma.sync.aligned.m16n8k16.row.col.f32.bf16.bf16.f32 "
        "{%0,%1,%2,%3}, {%4,%5,%6,%7}, {%8,%9}, {%0,%1,%2,%3};"
        : "+f"(c0), "+f"(c1), "+f"(c2), "+f"(c3)
        : "r"(a0), "r"(a1), "r"(a2), "r"(a3), "r"(b0), "r"(b1));
}

__device__ __forceinline__ void ldmx4(uint32_t* r, uint32_t a) {
    asm volatile(
        "ldmatrix.sync.aligned.m8n8.x4.shared.b16 {%0,%1,%2,%3}, [%4];"
        : "=r"(r[0]), "=r"(r[1]), "=r"(r[2]), "=r"(r[3]) : "r"(a));
}

__device__ __forceinline__ void ldmx4t(uint32_t* r, uint32_t a) {
    asm volatile(
        "ldmatrix.sync.aligned.m8n8.x4.trans.shared.b16 {%0,%1,%2,%3}, [%4];"
        : "=r"(r[0]), "=r"(r[1]), "=r"(r[2]), "=r"(r[3]) : "r"(a));
}

__device__ __forceinline__ void cp16(uint32_t dst, const void* src) {
    asm volatile("cp.async.cg.shared.global [%0], [%1], 16;"
                 :: "r"(dst), "l"(src));
}
#define CP_COMMIT() asm volatile("cp.async.commit_group;" ::: "memory")
#define CP_WAIT1()  asm volatile("cp.async.wait_group 1;" ::: "memory")
#define CP_WAIT0()  asm volatile("cp.async.wait_group 0;" ::: "memory")

__device__ __forceinline__ void split_pack(float x, float y,
                                           uint32_t& hi, uint32_t& lo) {
    __nv_bfloat162 h = __floats2bfloat162_rn(x, y);
    float2 f = __bfloat1622float2(h);
    __nv_bfloat162 l = __floats2bfloat162_rn(x - f.x, y - f.y);
    hi = *(uint32_t*)&h;
    lo = *(uint32_t*)&l;
}

// ---------------------------------------------------------------------------
// fused fp32 -> bf16 hi/lo split over all 7 tensors
// segs 0-2: inputs (8192 blocks each); segs 3-6: weights (1024 blocks each)
// ---------------------------------------------------------------------------
struct SplitArgs {
    const float* src[7];
    __nv_bfloat16* hi[7];
    __nv_bfloat16* lo[7];
};

__global__ __launch_bounds__(256)
void split_all(SplitArgs a)
{
    int bx = blockIdx.x;
    int seg, base;
    if (bx < 24576) { seg = bx >> 13;            base = bx & 8191; }
    else            { seg = 3 + ((bx - 24576) >> 10); base = (bx - 24576) & 1023; }
    int i = base * 256 + threadIdx.x;
    float4 v = ((const float4*)a.src[seg])[i];
    uint32_t h0, h1, l0, l1;
    split_pack(v.x, v.y, h0, l0);
    split_pack(v.z, v.w, h1, l1);
    ((uint2*)a.hi[seg])[i] = make_uint2(h0, h1);
    ((uint2*)a.lo[seg])[i] = make_uint2(l0, l1);
}

// ---------------------------------------------------------------------------
// bf16-split GEMM v4: 512 threads, warp tile 32x32, K-chunk 16,
// 3-stage cp.async with single barrier per chunk, ldmatrix fragments.
//   C = (Ah+Al)[M,K] @ (Wh+Wl)[N,K]^T + bias  (3-term split)
// ---------------------------------------------------------------------------
#define G_ROWB 48                    // bytes per smem row (16 bf16 + pad)
#define G_BUFB (128 * G_ROWB)        // 6144 B per buffer
#define G_STGB (4 * G_BUFB)          // 24576 B per stage (Ah,Al,Wh,Wl)
#define G_SMEM (3 * G_STGB)          // 73728 B

template<int LAYOUT>
__device__ __forceinline__ void gemm_core(
    const __nv_bfloat16* __restrict__ Ah_, const __nv_bfloat16* __restrict__ Al_,
    const __nv_bfloat16* __restrict__ Wh_, const __nv_bfloat16* __restrict__ Wl_,
    const float* __restrict__ bias,
    __nv_bfloat16* __restrict__ Chi, __nv_bfloat16* __restrict__ Clo,
    float* __restrict__ Cf, float scale)
{
    extern __shared__ __nv_bfloat16 smg[];
    const uint32_t smb = smem_u32(smg);

    const int tid = threadIdx.x;
    const int wid = tid >> 5;
    const int lane = tid & 31;
    const int group = lane >> 2;
    const int tg = lane & 3;
    const int wm = wid >> 2;         // 0..3, m offset /32
    const int wn = wid & 3;          // 0..3, n offset /32
    const int m0 = blockIdx.y * 128;
    const int n0 = blockIdx.x * 128;

    const int a_roff = ((lane >> 3) & 1) * 8 + (lane & 7);
    const int a_coff = (lane >> 4) * 8;
    const int b_roff = ((lane >> 4) & 1) * 8 + (lane & 7);
    const int b_coff = ((lane >> 3) & 1) * 8;

    // loader: 4 buffers x 128 rows x 32B; 2 x 16B per thread (512 threads)
    #define G_LOAD(CH, ST) do {                                                \
        uint32_t dbase = smb + (ST) * G_STGB;                                  \
        _Pragma("unroll")                                                      \
        for (int s2 = 0; s2 < 2; s2++) {                                       \
            int s = tid + s2 * 512;                                            \
            int a = s >> 8;                                                    \
            int rem = s & 255;                                                 \
            int row = rem >> 1, ch = rem & 1;                                  \
            const __nv_bfloat16* sp = (a == 0) ? Ah_ : (a == 1) ? Al_          \
                                     : (a == 2) ? Wh_ : Wl_;                   \
            int grow = ((a < 2) ? m0 : n0) + row;                              \
            cp16(dbase + a * G_BUFB + row * G_ROWB + ch * 16,                  \
                 sp + (size_t)grow * 1024 + (CH) * 16 + ch * 8);               \
        }                                                                      \
    } while (0)

    float c[2][4][4];
    #pragma unroll
    for (int mt = 0; mt < 2; mt++)
        #pragma unroll
        for (int nt = 0; nt < 4; nt++)
            #pragma unroll
            for (int r = 0; r < 4; r++) c[mt][nt][r] = 0.f;

    G_LOAD(0, 0); CP_COMMIT();
    G_LOAD(1, 1); CP_COMMIT();

    for (int i = 0; i < 64; i++) {
        if (i == 63) { CP_WAIT0(); } else { CP_WAIT1(); }
        __syncthreads();
        // load stage (i+2)%3 == (i-1)%3: all warps finished chunk i-1 (sync)
        if (i + 2 < 64) {
            G_LOAD(i + 2, (i + 2) % 3);
            CP_COMMIT();
        }

        const uint32_t sA = smb + (i % 3) * G_STGB;
        const uint32_t sW = sA + 2 * G_BUFB;

        uint32_t ah[2][4], al[2][4];
        #pragma unroll
        for (int mt = 0; mt < 2; mt++) {
            uint32_t addr = sA + (wm * 32 + mt * 16 + a_roff) * G_ROWB + a_coff * 2;
            ldmx4(ah[mt], addr);
            ldmx4(al[mt], addr + G_BUFB);
        }
        #pragma unroll
        for (int jj = 0; jj < 2; jj++) {
            uint32_t addr = sW + (wn * 32 + jj * 16 + b_roff) * G_ROWB + b_coff * 2;
            uint32_t bh4[4], bl4[4];
            ldmx4(bh4, addr);
            ldmx4(bl4, addr + G_BUFB);
            #pragma unroll
            for (int half = 0; half < 2; half++) {
                int nt = 2 * jj + half;
                uint32_t b0h = bh4[2 * half], b1h = bh4[2 * half + 1];
                uint32_t b0l = bl4[2 * half], b1l = bl4[2 * half + 1];
                #pragma unroll
                for (int mt = 0; mt < 2; mt++) {
                    float* cc = c[mt][nt];
                    mma_bf16(cc[0], cc[1], cc[2], cc[3],
                             ah[mt][0], ah[mt][1], ah[mt][2], ah[mt][3], b0h, b1h);
                    mma_bf16(cc[0], cc[1], cc[2], cc[3],
                             ah[mt][0], ah[mt][1], ah[mt][2], ah[mt][3], b0l, b1l);
                    mma_bf16(cc[0], cc[1], cc[2], cc[3],
                             al[mt][0], al[mt][1], al[mt][2], al[mt][3], b0h, b1h);
                }
            }
        }
    }

    // epilogue
    #pragma unroll
    for (int mt = 0; mt < 2; mt++) {
        #pragma unroll
        for (int nt = 0; nt < 4; nt++) {
            int col = n0 + wn * 32 + nt * 8 + 2 * tg;
            float bx = bias[col], by = bias[col + 1];
            #pragma unroll
            for (int half = 0; half < 2; half++) {
                int row = m0 + wm * 32 + mt * 16 + group + half * 8;
                float vx = c[mt][nt][half * 2 + 0] + bx;
                float vy = c[mt][nt][half * 2 + 1] + by;
                if (LAYOUT == 1) {
                    *(float2*)(Cf + (size_t)row * 1024 + col) = make_float2(vx, vy);
                } else {
                    vx *= scale; vy *= scale;
                    int b = row >> 11;
                    int t = row & 2047;
                    int h = col >> 6;
                    int hd = col & 63;
                    size_t addr = ((size_t)(b * H_ + h) * T_ + t) * HD_ + hd;
                    uint32_t hi, lo;
                    split_pack(vx, vy, hi, lo);
                    *(uint32_t*)(Chi + addr) = hi;
                    *(uint32_t*)(Clo + addr) = lo;
                }
            }
        }
    }
}

struct QKVArgs {
    const __nv_bfloat16 *ah[3], *al[3], *wh[3], *wl[3];
    const float* bias[3];
    __nv_bfloat16 *ch[3], *cl[3];
};

__global__ __launch_bounds__(512)
void gemm_qkv(QKVArgs p)
{
    int z = blockIdx.z;
    gemm_core<0>(p.ah[z], p.al[z], p.wh[z], p.wl[z], p.bias[z],
                 p.ch[z], p.cl[z], nullptr, (z == 0) ? SCALE_ : 1.0f);
}

__global__ __launch_bounds__(512)
void gemm_o(const __nv_bfloat16* ah, const __nv_bfloat16* al,
            const __nv_bfloat16* wh, const __nv_bfloat16* wl,
            const float* bias, float* out)
{
    gemm_core<1>(ah, al, wh, wl, bias, nullptr, nullptr, out, 1.0f);
}

// ---------------------------------------------------------------------------
// Tensor-core flash attention (causal), ldmatrix K + trans-V — R6 proven.
// ---------------------------------------------------------------------------
#define AT_ROWB 144
#define AT_TILE (64 * AT_ROWB)
#define AT_STAGE (4 * AT_TILE)
#define AT_SMEM (2 * AT_STAGE)

__global__ __launch_bounds__(256, 1)
void attn_mma()
{
    extern __shared__ char smraw[];
    const uint32_t smb = smem_u32(smraw);
    const int tid = threadIdx.x;
    const int w = tid >> 5;
    const int lane = tid & 31;
    const int g = lane >> 2;
    const int tg = lane & 3;
    const int qt = 15 - blockIdx.x;
    const int bh = blockIdx.y;
    const int b = bh >> 4;
    const int h = bh & 15;

    const int r0 = qt * 128 + w * 16 + g;

    const int kb_roff = ((lane >> 4) & 1) * 8 + (lane & 7);
    const int kb_coff = ((lane >> 3) & 1) * 8;

    const __nv_bfloat16* qhp = g_qh + (size_t)bh * T_ * HD_;
    const __nv_bfloat16* qlp = g_ql + (size_t)bh * T_ * HD_;
    uint32_t qfh[4][4], qfl[4][4];
    #pragma unroll
    for (int ks = 0; ks < 4; ks++) {
        int d = ks * 16 + 2 * tg;
        size_t a0 = (size_t)r0 * HD_ + d;
        size_t a1 = (size_t)(r0 + 8) * HD_ + d;
        qfh[ks][0] = *(const uint32_t*)(qhp + a0);
        qfh[ks][1] = *(const uint32_t*)(qhp + a1);
        qfh[ks][2] = *(const uint32_t*)(qhp + a0 + 8);
        qfh[ks][3] = *(const uint32_t*)(qhp + a1 + 8);
        qfl[ks][0] = *(const uint32_t*)(qlp + a0);
        qfl[ks][1] = *(const uint32_t*)(qlp + a1);
        qfl[ks][2] = *(const uint32_t*)(qlp + a0 + 8);
        qfl[ks][3] = *(const uint32_t*)(qlp + a1 + 8);
    }

    const __nv_bfloat16* khp = g_kh + (size_t)bh * T_ * HD_;
    const __nv_bfloat16* klp = g_kl + (size_t)bh * T_ * HD_;
    const __nv_bfloat16* vhp = g_vh + (size_t)bh * T_ * HD_;
    const __nv_bfloat16* vlp = g_vl + (size_t)bh * T_ * HD_;

    float o[8][4];
    #pragma unroll
    for (int j = 0; j < 8; j++)
        #pragma unroll
        for (int r = 0; r < 4; r++) o[j][r] = 0.f;
    float m0 = -1e30f, m1 = -1e30f, l0 = 0.f, l1 = 0.f;

    const int nkt = 2 * qt + 2;
    const int last_kt = (qt * 128 + w * 16 + 15) >> 6;

    #define LOAD_TILE(KT, S) do {                                              \
        uint32_t dbase = smb + (S) * AT_STAGE;                                 \
        size_t toff = (size_t)(KT) * 64 * HD_;                                 \
        _Pragma("unroll")                                                      \
        for (int i = 0; i < 8; i++) {                                          \
            const __nv_bfloat16* sp = (i < 2) ? khp : (i < 4) ? klp            \
                                     : (i < 6) ? vhp : vlp;                    \
            int a = i >> 1;                                                    \
            int rem = ((i & 1) << 8) + tid;                                    \
            int row = rem >> 3, ch = rem & 7;                                  \
            cp16(dbase + a * AT_TILE + row * AT_ROWB + ch * 16,                \
                 sp + toff + (size_t)row * HD_ + ch * 8);                      \
        }                                                                      \
    } while (0)

    LOAD_TILE(0, 0);
    CP_COMMIT();

    for (int kt = 0; kt < nkt; kt++) {
        if (kt + 1 < nkt) {
            LOAD_TILE(kt + 1, (kt + 1) & 1);
            CP_COMMIT();
            CP_WAIT1();
        } else {
            CP_WAIT0();
        }
        __syncthreads();

        if (kt <= last_kt) {
            const uint32_t Kh = smb + (kt & 1) * AT_STAGE;
            const uint32_t Vh = Kh + 2 * AT_TILE;

            float sc[8][4];
            #pragma unroll
            for (int j = 0; j < 8; j++)
                #pragma unroll
                for (int r = 0; r < 4; r++) sc[j][r] = 0.f;

            #pragma unroll
            for (int ks = 0; ks < 4; ks++) {
                #pragma unroll
                for (int jj = 0; jj < 4; jj++) {
                    uint32_t addr = Kh + (16 * jj + kb_roff) * AT_ROWB
                                       + (16 * ks + kb_coff) * 2;
                    uint32_t kh4[4], kl4[4];
                    ldmx4(kh4, addr);
                    ldmx4(kl4, addr + AT_TILE);
                    #pragma unroll
                    for (int half = 0; half < 2; half++) {
                        float* cc = sc[2 * jj + half];
                        uint32_t b0h = kh4[2 * half], b1h = kh4[2 * half + 1];
                        uint32_t b0l = kl4[2 * half], b1l = kl4[2 * half + 1];
                        mma_bf16(cc[0], cc[1], cc[2], cc[3],
                                 qfh[ks][0], qfh[ks][1], qfh[ks][2], qfh[ks][3], b0h, b1h);
                        mma_bf16(cc[0], cc[1], cc[2], cc[3],
                                 qfh[ks][0], qfh[ks][1], qfh[ks][2], qfh[ks][3], b0l, b1l);
                        mma_bf16(cc[0], cc[1], cc[2], cc[3],
                                 qfl[ks][0], qfl[ks][1], qfl[ks][2], qfl[ks][3], b0h, b1h);
                    }
                }
            }

            if (kt == last_kt) {
                #pragma unroll
                for (int j = 0; j < 8; j++) {
                    int cgl = kt * 64 + 8 * j + 2 * tg;
                    if (cgl     > r0)     sc[j][0] = -1e30f;
                    if (cgl + 1 > r0)     sc[j][1] = -1e30f;
                    if (cgl     > r0 + 8) sc[j][2] = -1e30f;
                    if (cgl + 1 > r0 + 8) sc[j][3] = -1e30f;
                }
            }

            float mx0 = -1e30f, mx1 = -1e30f;
            #pragma unroll
            for (int j = 0; j < 8; j++) {
                mx0 = fmaxf(mx0, fmaxf(sc[j][0], sc[j][1]));
                mx1 = fmaxf(mx1, fmaxf(sc[j][2], sc[j][3]));
            }
            mx0 = fmaxf(mx0, __shfl_xor_sync(0xffffffffu, mx0, 1));
            mx0 = fmaxf(mx0, __shfl_xor_sync(0xffffffffu, mx0, 2));
            mx1 = fmaxf(mx1, __shfl_xor_sync(0xffffffffu, mx1, 1));
            mx1 = fmaxf(mx1, __shfl_xor_sync(0xffffffffu, mx1, 2));
            float mn0 = fmaxf(m0, mx0), mn1 = fmaxf(m1, mx1);
            float al0 = __expf(m0 - mn0), al1 = __expf(m1 - mn1);
            float ps0 = 0.f, ps1 = 0.f;
            #pragma unroll
            for (int j = 0; j < 8; j++) {
                sc[j][0] = __expf(sc[j][0] - mn0);
                sc[j][1] = __expf(sc[j][1] - mn0);
                sc[j][2] = __expf(sc[j][2] - mn1);
                sc[j][3] = __expf(sc[j][3] - mn1);
                ps0 += sc[j][0] + sc[j][1];
                ps1 += sc[j][2] + sc[j][3];
            }
            ps0 += __shfl_xor_sync(0xffffffffu, ps0, 1);
            ps0 += __shfl_xor_sync(0xffffffffu, ps0, 2);
            ps1 += __shfl_xor_sync(0xffffffffu, ps1, 1);
            ps1 += __shfl_xor_sync(0xffffffffu, ps1, 2);
            l0 = l0 * al0 + ps0;  m0 = mn0;
            l1 = l1 * al1 + ps1;  m1 = mn1;
            #pragma unroll
            for (int j = 0; j < 8; j++) {
                o[j][0] *= al0; o[j][1] *= al0;
                o[j][2] *= al1; o[j][3] *= al1;
            }

            const uint32_t vrow =
                Vh + (lane & 15) * AT_ROWB + ((lane >> 4) * 8) * 2;
            #pragma unroll
            for (int kk = 0; kk < 4; kk++) {
                uint32_t ph[4], pl[4];
                split_pack(sc[2*kk][0],   sc[2*kk][1],   ph[0], pl[0]);
                split_pack(sc[2*kk][2],   sc[2*kk][3],   ph[1], pl[1]);
                split_pack(sc[2*kk+1][0], sc[2*kk+1][1], ph[2], pl[2]);
                split_pack(sc[2*kk+1][2], sc[2*kk+1][3], ph[3], pl[3]);
                uint32_t rbase = vrow + 16 * kk * AT_ROWB;
                #pragma unroll
                for (int jp = 0; jp < 4; jp++) {
                    uint32_t bh4[4], bl4[4];
                    uint32_t ad = rbase + (16 * jp) * 2;
                    ldmx4t(bh4, ad);
                    ldmx4t(bl4, ad + AT_TILE);
                    float* o0 = o[2 * jp];
                    float* o1 = o[2 * jp + 1];
                    mma_bf16(o0[0], o0[1], o0[2], o0[3],
                             ph[0], ph[1], ph[2], ph[3], bh4[0], bh4[1]);
                    mma_bf16(o0[0], o0[1], o0[2], o0[3],
                             ph[0], ph[1], ph[2], ph[3], bl4[0], bl4[1]);
                    mma_bf16(o0[0], o0[1], o0[2], o0[3],
                             pl[0], pl[1], pl[2], pl[3], bh4[0], bh4[1]);
                    mma_bf16(o1[0], o1[1], o1[2], o1[3],
                             ph[0], ph[1], ph[2], ph[3], bh4[2], bh4[3]);
                    mma_bf16(o1[0], o1[1], o1[2], o1[3],
                             ph[0], ph[1], ph[2], ph[3], bl4[2], bl4[3]);
                    mma_bf16(o1[0], o1[1], o1[2], o1[3],
                             pl[0], pl[1], pl[2], pl[3], bh4[2], bh4[3]);
                }
            }
        }
        __syncthreads();
    }

    float i0 = 1.f / l0, i1 = 1.f / l1;
    size_t base0 = ((size_t)(b * T_ + r0)) * D_ + h * HD_;
    size_t base1 = ((size_t)(b * T_ + r0 + 8)) * D_ + h * HD_;
    #pragma unroll
    for (int j = 0; j < 8; j++) {
        int d = 8 * j + 2 * tg;
        uint32_t hi, lo;
        split_pack(o[j][0] * i0, o[j][1] * i0, hi, lo);
        *(uint32_t*)(g_ah + base0 + d) = hi;
        *(uint32_t*)(g_al + base0 + d) = lo;
        split_pack(o[j][2] * i1, o[j][3] * i1, hi, lo);
        *(uint32_t*)(g_ah + base1 + d) = hi;
        *(uint32_t*)(g_al + base1 + d) = lo;
    }
}

// ---------------------------------------------------------------------------
extern "C" void kernel_launch(void* const* d_in, const int* in_sizes, int n_in,
                              void* d_out, int out_size)
{
    const float* query = (const float*)d_in[0];
    const float* key   = (const float*)d_in[1];
    const float* value = (const float*)d_in[2];
    const float* Wq    = (const float*)d_in[3];
    const float* bq    = (const float*)d_in[4];
    const float* Wk    = (const float*)d_in[5];
    const float* bk    = (const float*)d_in[6];
    const float* Wv    = (const float*)d_in[7];
    const float* bv    = (const float*)d_in[8];
    const float* Wo    = (const float*)d_in[9];
    const float* bo    = (const float*)d_in[10];
    float* out = (float*)d_out;

    __nv_bfloat16 *xqh, *xql, *xkh, *xkl, *xvh, *xvl;
    __nv_bfloat16 *wqh, *wql, *wkh, *wkl, *wvh, *wvl, *woh, *wol;
    __nv_bfloat16 *qh, *ql, *kh, *kl, *vh, *vl, *ah, *al;
    cudaGetSymbolAddress((void**)&xqh, g_xqh); cudaGetSymbolAddress((void**)&xql, g_xql);
    cudaGetSymbolAddress((void**)&xkh, g_xkh); cudaGetSymbolAddress((void**)&xkl, g_xkl);
    cudaGetSymbolAddress((void**)&xvh, g_xvh); cudaGetSymbolAddress((void**)&xvl, g_xvl);
    cudaGetSymbolAddress((void**)&wqh, g_wqh); cudaGetSymbolAddress((void**)&wql, g_wql);
    cudaGetSymbolAddress((void**)&wkh, g_wkh); cudaGetSymbolAddress((void**)&wkl, g_wkl);
    cudaGetSymbolAddress((void**)&wvh, g_wvh); cudaGetSymbolAddress((void**)&wvl, g_wvl);
    cudaGetSymbolAddress((void**)&woh, g_woh); cudaGetSymbolAddress((void**)&wol, g_wol);
    cudaGetSymbolAddress((void**)&qh, g_qh);   cudaGetSymbolAddress((void**)&ql, g_ql);
    cudaGetSymbolAddress((void**)&kh, g_kh);   cudaGetSymbolAddress((void**)&kl, g_kl);
    cudaGetSymbolAddress((void**)&vh, g_vh);   cudaGetSymbolAddress((void**)&vl, g_vl);
    cudaGetSymbolAddress((void**)&ah, g_ah);   cudaGetSymbolAddress((void**)&al, g_al);

    cudaFuncSetAttribute(gemm_qkv, cudaFuncAttributeMaxDynamicSharedMemorySize, G_SMEM);
    cudaFuncSetAttribute(gemm_o,   cudaFuncAttributeMaxDynamicSharedMemorySize, G_SMEM);
    cudaFuncSetAttribute(attn_mma, cudaFuncAttributeMaxDynamicSharedMemorySize, AT_SMEM);

    // fused split: segs 0-2 inputs, 3-6 weights
    SplitArgs sa;
    sa.src[0] = query; sa.hi[0] = xqh; sa.lo[0] = xql;
    sa.src[1] = key;   sa.hi[1] = xkh; sa.lo[1] = xkl;
    sa.src[2] = value; sa.hi[2] = xvh; sa.lo[2] = xvl;
    sa.src[3] = Wq;    sa.hi[3] = wqh; sa.lo[3] = wql;
    sa.src[4] = Wk;    sa.hi[4] = wkh; sa.lo[4] = wkl;
    sa.src[5] = Wv;    sa.hi[5] = wvh; sa.lo[5] = wvl;
    sa.src[6] = Wo;    sa.hi[6] = woh; sa.lo[6] = wol;
    split_all<<<28672, 256>>>(sa);

    // fused QKV projections
    QKVArgs qa;
    qa.ah[0] = xqh; qa.al[0] = xql; qa.wh[0] = wqh; qa.wl[0] = wql;
    qa.bias[0] = bq; qa.ch[0] = qh; qa.cl[0] = ql;
    qa.ah[1] = xkh; qa.al[1] = xkl; qa.wh[1] = wkh; qa.wl[1] = wkl;
    qa.bias[1] = bk; qa.ch[1] = kh; qa.cl[1] = kl;
    qa.ah[2] = xvh; qa.al[2] = xvl; qa.wh[2] = wvh; qa.wl[2] = wvl;
    qa.bias[2] = bv; qa.ch[2] = vh; qa.cl[2] = vl;
    gemm_qkv<<<dim3(8, 64, 3), 512, G_SMEM>>>(qa);

    attn_mma<<<dim3(16, B_ * H_), 256, AT_SMEM>>>();

    gemm_o<<<dim3(8, 64, 1), 512, G_SMEM>>>(ah, al, woh, wol, bo, out);
}

// round 8
// speedup vs baseline: 1.1694x; 1.1694x over previous
#include <cuda_runtime.h>
#include <cuda_bf16.h>
#include <math.h>
#include <stdint.h>

#define B_   4
#define T_   2048
#define D_   1024
#define H_   16
#define HD_  64
#define M_   (B_ * T_)
#define SCALE_ 0.125f

// ---------------- scratch (device globals; no allocation allowed) ----------
__device__ __nv_bfloat16 g_xqh[(size_t)M_ * D_], g_xql[(size_t)M_ * D_];
__device__ __nv_bfloat16 g_xkh[(size_t)M_ * D_], g_xkl[(size_t)M_ * D_];
__device__ __nv_bfloat16 g_xvh[(size_t)M_ * D_], g_xvl[(size_t)M_ * D_];
__device__ __nv_bfloat16 g_wqh[(size_t)D_ * D_], g_wql[(size_t)D_ * D_];
__device__ __nv_bfloat16 g_wkh[(size_t)D_ * D_], g_wkl[(size_t)D_ * D_];
__device__ __nv_bfloat16 g_wvh[(size_t)D_ * D_], g_wvl[(size_t)D_ * D_];
__device__ __nv_bfloat16 g_woh[(size_t)D_ * D_], g_wol[(size_t)D_ * D_];
__device__ __nv_bfloat16 g_qh[(size_t)B_ * H_ * T_ * HD_], g_ql[(size_t)B_ * H_ * T_ * HD_];
__device__ __nv_bfloat16 g_kh[(size_t)B_ * H_ * T_ * HD_], g_kl[(size_t)B_ * H_ * T_ * HD_];
__device__ __nv_bfloat16 g_vh[(size_t)B_ * H_ * T_ * HD_], g_vl[(size_t)B_ * H_ * T_ * HD_];
__device__ __nv_bfloat16 g_ah[(size_t)M_ * D_], g_al[(size_t)M_ * D_];

// =========================== helpers ========================================
__device__ __forceinline__ uint32_t smem_u32(const void* p) {
    uint32_t a;
    asm("{ .reg .u64 t; cvta.to.shared.u64 t, %1; cvt.u32.u64 %0, t; }"
        : "=r"(a) : "l"(p));
    return a;
}

__device__ __forceinline__ void mma_bf16(
    float& c0, float& c1, float& c2, float& c3,
    uint32_t a0, uint32_t a1, uint32_t a2, uint32_t a3,
    uint32_t b0, uint32_t b1)
{
    asm volatile(
        "mma.sync.aligned.m16n8k16.row.col.f32.bf16.bf16.f32 "
        "{%0,%1,%2,%3}, {%4,%5,%6,%7}, {%8,%9}, {%0,%1,%2,%3};"
        : "+f"(c0), "+f"(c1), "+f"(c2), "+f"(c3)
        : "r"(a0), "r"(a1), "r"(a2), "r"(a3), "r"(b0), "r"(b1));
}

__device__ __forceinline__ void ldmx4(uint32_t* r, uint32_t a) {
    asm volatile(
        "ldmatrix.sync.aligned.m8n8.x4.shared.b16 {%0,%1,%2,%3}, [%4];"
        : "=r"(r[0]), "=r"(r[1]), "=r"(r[2]), "=r"(r[3]) : "r"(a));
}

__device__ __forceinline__ void ldmx4t(uint32_t* r, uint32_t a) {
    asm volatile(
        "ldmatrix.sync.aligned.m8n8.x4.trans.shared.b16 {%0,%1,%2,%3}, [%4];"
        : "=r"(r[0]), "=r"(r[1]), "=r"(r[2]), "=r"(r[3]) : "r"(a));
}

__device__ __forceinline__ void cp16(uint32_t dst, const void* src) {
    asm volatile("cp.async.cg.shared.global [%0], [%1], 16;"
                 :: "r"(dst), "l"(src));
}
#define CP_COMMIT() asm volatile("cp.async.commit_group;" ::: "memory")
#define CP_WAIT1()  asm volatile("cp.async.wait_group 1;" ::: "memory")
#define CP_WAIT0()  asm volatile("cp.async.wait_group 0;" ::: "memory")

__device__ __forceinline__ void split_pack(float x, float y,
                                           uint32_t& hi, uint32_t& lo) {
    __nv_bfloat162 h = __floats2bfloat162_rn(x, y);
    float2 f = __bfloat1622float2(h);
    __nv_bfloat162 l = __floats2bfloat162_rn(x - f.x, y - f.y);
    hi = *(uint32_t*)&h;
    lo = *(uint32_t*)&l;
}

// ---------------------------------------------------------------------------
// fused fp32 -> bf16 hi/lo split over all 7 tensors
// segs 0-2: inputs (8192 blocks each); segs 3-6: weights (1024 blocks each)
// ---------------------------------------------------------------------------
struct SplitArgs {
    const float* src[7];
    __nv_bfloat16* hi[7];
    __nv_bfloat16* lo[7];
};

__global__ __launch_bounds__(256)
void split_all(SplitArgs a)
{
    int bx = blockIdx.x;
    int seg, base;
    if (bx < 24576) { seg = bx >> 13;            base = bx & 8191; }
    else            { seg = 3 + ((bx - 24576) >> 10); base = (bx - 24576) & 1023; }
    int i = base * 256 + threadIdx.x;
    float4 v = ((const float4*)a.src[seg])[i];
    uint32_t h0, h1, l0, l1;
    split_pack(v.x, v.y, h0, l0);
    split_pack(v.z, v.w, h1, l1);
    ((uint2*)a.hi[seg])[i] = make_uint2(h0, h1);
    ((uint2*)a.lo[seg])[i] = make_uint2(l0, l1);
}

// ---------------------------------------------------------------------------
// bf16-split GEMM (R6-proven shape): 256 threads, warp tile 32x64, K-chunk 32,
// 2-stage cp.async, ldmatrix fragments.
//   C = (Ah+Al)[M,K] @ (Wh+Wl)[N,K]^T + bias  (3-term split)
// ---------------------------------------------------------------------------
#define G_LDB 40
#define G_BUF (128 * G_LDB)
#define G_STAGE_B (4 * G_BUF * 2)    // 40960
#define G_SMEM (2 * G_STAGE_B)       // 81920

template<int LAYOUT>
__device__ __forceinline__ void gemm_core(
    const __nv_bfloat16* __restrict__ Ah_, const __nv_bfloat16* __restrict__ Al_,
    const __nv_bfloat16* __restrict__ Wh_, const __nv_bfloat16* __restrict__ Wl_,
    const float* __restrict__ bias,
    __nv_bfloat16* __restrict__ Chi, __nv_bfloat16* __restrict__ Clo,
    float* __restrict__ Cf, float scale)
{
    extern __shared__ __nv_bfloat16 smg[];
    const uint32_t smb = smem_u32(smg);

    const int tid = threadIdx.x;
    const int wid = tid >> 5;
    const int lane = tid & 31;
    const int group = lane >> 2;
    const int tg = lane & 3;
    const int wm = wid >> 1;
    const int wn = wid & 1;
    const int m0 = blockIdx.y * 128;
    const int n0 = blockIdx.x * 128;

    const int a_roff = ((lane >> 3) & 1) * 8 + (lane & 7);
    const int a_coff = (lane >> 4) * 8;
    const int b_roff = ((lane >> 4) & 1) * 8 + (lane & 7);
    const int b_coff = ((lane >> 3) & 1) * 8;

    #define G_LOAD(CHUNK, STAGE) do {                                          \
        uint32_t dbase = smb + (STAGE) * G_STAGE_B;                            \
        int k0 = (CHUNK) * 32;                                                 \
        _Pragma("unroll")                                                      \
        for (int i = 0; i < 8; i++) {                                          \
            int a = i >> 1;                                                    \
            int rem = ((i & 1) << 8) + tid;                                    \
            int row = rem >> 2, ch = rem & 3;                                  \
            const __nv_bfloat16* sp = (a == 0) ? Ah_ : (a == 1) ? Al_          \
                                     : (a == 2) ? Wh_ : Wl_;                   \
            int grow = ((a < 2) ? m0 : n0) + row;                              \
            cp16(dbase + a * (G_BUF * 2) + row * 80 + ch * 16,                 \
                 sp + (size_t)grow * 1024 + k0 + ch * 8);                      \
        }                                                                      \
    } while (0)

    float c[2][8][4];
    #pragma unroll
    for (int mt = 0; mt < 2; mt++)
        #pragma unroll
        for (int nt = 0; nt < 8; nt++)
            #pragma unroll
            for (int r = 0; r < 4; r++) c[mt][nt][r] = 0.f;

    G_LOAD(0, 0); CP_COMMIT();

    for (int chunk = 0; chunk < 32; chunk++) {
        if (chunk + 1 < 32) {
            G_LOAD(chunk + 1, (chunk + 1) & 1);
            CP_COMMIT();
            CP_WAIT1();
        } else {
            CP_WAIT0();
        }
        __syncthreads();

        const uint32_t sA = smb + (chunk & 1) * G_STAGE_B;
        const uint32_t sW = sA + 2 * (G_BUF * 2);
        const uint32_t dHL = G_BUF * 2;

        #pragma unroll
        for (int ks = 0; ks < 2; ks++) {
            const int koff = ks * 16;
            uint32_t ah[2][4], al[2][4];
            #pragma unroll
            for (int mt = 0; mt < 2; mt++) {
                uint32_t addr = sA +
                    ((wm * 32 + mt * 16 + a_roff) * G_LDB + koff + a_coff) * 2;
                ldmx4(ah[mt], addr);
                ldmx4(al[mt], addr + dHL);
            }
            #pragma unroll
            for (int jj = 0; jj < 4; jj++) {
                uint32_t addr = sW +
                    ((wn * 64 + jj * 16 + b_roff) * G_LDB + koff + b_coff) * 2;
                uint32_t bh4[4], bl4[4];
                ldmx4(bh4, addr);
                ldmx4(bl4, addr + dHL);
                #pragma unroll
                for (int half = 0; half < 2; half++) {
                    int nt = 2 * jj + half;
                    uint32_t b0h = bh4[2 * half], b1h = bh4[2 * half + 1];
                    uint32_t b0l = bl4[2 * half], b1l = bl4[2 * half + 1];
                    #pragma unroll
                    for (int mt = 0; mt < 2; mt++) {
                        float* cc = c[mt][nt];
                        mma_bf16(cc[0], cc[1], cc[2], cc[3],
                                 ah[mt][0], ah[mt][1], ah[mt][2], ah[mt][3], b0h, b1h);
                        mma_bf16(cc[0], cc[1], cc[2], cc[3],
                                 ah[mt][0], ah[mt][1], ah[mt][2], ah[mt][3], b0l, b1l);
                        mma_bf16(cc[0], cc[1], cc[2], cc[3],
                                 al[mt][0], al[mt][1], al[mt][2], al[mt][3], b0h, b1h);
                    }
                }
            }
        }
        __syncthreads();
    }

    // epilogue
    #pragma unroll
    for (int mt = 0; mt < 2; mt++) {
        #pragma unroll
        for (int nt = 0; nt < 8; nt++) {
            int col = n0 + wn * 64 + nt * 8 + 2 * tg;
            float bx = bias[col], by = bias[col + 1];
            #pragma unroll
            for (int half = 0; half < 2; half++) {
                int row = m0 + wm * 32 + mt * 16 + group + half * 8;
                float vx = c[mt][nt][half * 2 + 0] + bx;
                float vy = c[mt][nt][half * 2 + 1] + by;
                if (LAYOUT == 1) {
                    *(float2*)(Cf + (size_t)row * 1024 + col) = make_float2(vx, vy);
                } else {
                    vx *= scale; vy *= scale;
                    int b = row >> 11;
                    int t = row & 2047;
                    int h = col >> 6;
                    int hd = col & 63;
                    size_t addr = ((size_t)(b * H_ + h) * T_ + t) * HD_ + hd;
                    uint32_t hi, lo;
                    split_pack(vx, vy, hi, lo);
                    *(uint32_t*)(Chi + addr) = hi;
                    *(uint32_t*)(Clo + addr) = lo;
                }
            }
        }
    }
}

struct QKVArgs {
    const __nv_bfloat16 *ah[3], *al[3], *wh[3], *wl[3];
    const float* bias[3];
    __nv_bfloat16 *ch[3], *cl[3];
};

__global__ __launch_bounds__(256)
void gemm_qkv(QKVArgs p)
{
    int z = blockIdx.z;
    gemm_core<0>(p.ah[z], p.al[z], p.wh[z], p.wl[z], p.bias[z],
                 p.ch[z], p.cl[z], nullptr, (z == 0) ? SCALE_ : 1.0f);
}

__global__ __launch_bounds__(256)
void gemm_o(const __nv_bfloat16* ah, const __nv_bfloat16* al,
            const __nv_bfloat16* wh, const __nv_bfloat16* wl,
            const float* bias, float* out)
{
    gemm_core<1>(ah, al, wh, wl, bias, nullptr, nullptr, out, 1.0f);
}

// ---------------------------------------------------------------------------
// Tensor-core flash attention (causal), ldmatrix K + trans-V — R6 proven.
// ---------------------------------------------------------------------------
#define AT_ROWB 144
#define AT_TILE (64 * AT_ROWB)
#define AT_STAGE (4 * AT_TILE)
#define AT_SMEM (2 * AT_STAGE)

__global__ __launch_bounds__(256, 1)
void attn_mma()
{
    extern __shared__ char smraw[];
    const uint32_t smb = smem_u32(smraw);
    const int tid = threadIdx.x;
    const int w = tid >> 5;
    const int lane = tid & 31;
    const int g = lane >> 2;
    const int tg = lane & 3;
    const int qt = 15 - blockIdx.x;
    const int bh = blockIdx.y;
    const int b = bh >> 4;
    const int h = bh & 15;

    const int r0 = qt * 128 + w * 16 + g;

    const int kb_roff = ((lane >> 4) & 1) * 8 + (lane & 7);
    const int kb_coff = ((lane >> 3) & 1) * 8;

    const __nv_bfloat16* qhp = g_qh + (size_t)bh * T_ * HD_;
    const __nv_bfloat16* qlp = g_ql + (size_t)bh * T_ * HD_;
    uint32_t qfh[4][4], qfl[4][4];
    #pragma unroll
    for (int ks = 0; ks < 4; ks++) {
        int d = ks * 16 + 2 * tg;
        size_t a0 = (size_t)r0 * HD_ + d;
        size_t a1 = (size_t)(r0 + 8) * HD_ + d;
        qfh[ks][0] = *(const uint32_t*)(qhp + a0);
        qfh[ks][1] = *(const uint32_t*)(qhp + a1);
        qfh[ks][2] = *(const uint32_t*)(qhp + a0 + 8);
        qfh[ks][3] = *(const uint32_t*)(qhp + a1 + 8);
        qfl[ks][0] = *(const uint32_t*)(qlp + a0);
        qfl[ks][1] = *(const uint32_t*)(qlp + a1);
        qfl[ks][2] = *(const uint32_t*)(qlp + a0 + 8);
        qfl[ks][3] = *(const uint32_t*)(qlp + a1 + 8);
    }

    const __nv_bfloat16* khp = g_kh + (size_t)bh * T_ * HD_;
    const __nv_bfloat16* klp = g_kl + (size_t)bh * T_ * HD_;
    const __nv_bfloat16* vhp = g_vh + (size_t)bh * T_ * HD_;
    const __nv_bfloat16* vlp = g_vl + (size_t)bh * T_ * HD_;

    float o[8][4];
    #pragma unroll
    for (int j = 0; j < 8; j++)
        #pragma unroll
        for (int r = 0; r < 4; r++) o[j][r] = 0.f;
    float m0 = -1e30f, m1 = -1e30f, l0 = 0.f, l1 = 0.f;

    const int nkt = 2 * qt + 2;
    const int last_kt = (qt * 128 + w * 16 + 15) >> 6;

    #define LOAD_TILE(KT, S) do {                                              \
        uint32_t dbase = smb + (S) * AT_STAGE;                                 \
        size_t toff = (size_t)(KT) * 64 * HD_;                                 \
        _Pragma("unroll")                                                      \
        for (int i = 0; i < 8; i++) {                                          \
            const __nv_bfloat16* sp = (i < 2) ? khp : (i < 4) ? klp            \
                                     : (i < 6) ? vhp : vlp;                    \
            int a = i >> 1;                                                    \
            int rem = ((i & 1) << 8) + tid;                                    \
            int row = rem >> 3, ch = rem & 7;                                  \
            cp16(dbase + a * AT_TILE + row * AT_ROWB + ch * 16,                \
                 sp + toff + (size_t)row * HD_ + ch * 8);                      \
        }                                                                      \
    } while (0)

    LOAD_TILE(0, 0);
    CP_COMMIT();

    for (int kt = 0; kt < nkt; kt++) {
        if (kt + 1 < nkt) {
            LOAD_TILE(kt + 1, (kt + 1) & 1);
            CP_COMMIT();
            CP_WAIT1();
        } else {
            CP_WAIT0();
        }
        __syncthreads();

        if (kt <= last_kt) {
            const uint32_t Kh = smb + (kt & 1) * AT_STAGE;
            const uint32_t Vh = Kh + 2 * AT_TILE;

            float sc[8][4];
            #pragma unroll
            for (int j = 0; j < 8; j++)
                #pragma unroll
                for (int r = 0; r < 4; r++) sc[j][r] = 0.f;

            #pragma unroll
            for (int ks = 0; ks < 4; ks++) {
                #pragma unroll
                for (int jj = 0; jj < 4; jj++) {
                    uint32_t addr = Kh + (16 * jj + kb_roff) * AT_ROWB
                                       + (16 * ks + kb_coff) * 2;
                    uint32_t kh4[4], kl4[4];
                    ldmx4(kh4, addr);
                    ldmx4(kl4, addr + AT_TILE);
                    #pragma unroll
                    for (int half = 0; half < 2; half++) {
                        float* cc = sc[2 * jj + half];
                        uint32_t b0h = kh4[2 * half], b1h = kh4[2 * half + 1];
                        uint32_t b0l = kl4[2 * half], b1l = kl4[2 * half + 1];
                        mma_bf16(cc[0], cc[1], cc[2], cc[3],
                                 qfh[ks][0], qfh[ks][1], qfh[ks][2], qfh[ks][3], b0h, b1h);
                        mma_bf16(cc[0], cc[1], cc[2], cc[3],
                                 qfh[ks][0], qfh[ks][1], qfh[ks][2], qfh[ks][3], b0l, b1l);
                        mma_bf16(cc[0], cc[1], cc[2], cc[3],
                                 qfl[ks][0], qfl[ks][1], qfl[ks][2], qfl[ks][3], b0h, b1h);
                    }
                }
            }

            if (kt == last_kt) {
                #pragma unroll
                for (int j = 0; j < 8; j++) {
                    int cgl = kt * 64 + 8 * j + 2 * tg;
                    if (cgl     > r0)     sc[j][0] = -1e30f;
                    if (cgl + 1 > r0)     sc[j][1] = -1e30f;
                    if (cgl     > r0 + 8) sc[j][2] = -1e30f;
                    if (cgl + 1 > r0 + 8) sc[j][3] = -1e30f;
                }
            }

            float mx0 = -1e30f, mx1 = -1e30f;
            #pragma unroll
            for (int j = 0; j < 8; j++) {
                mx0 = fmaxf(mx0, fmaxf(sc[j][0], sc[j][1]));
                mx1 = fmaxf(mx1, fmaxf(sc[j][2], sc[j][3]));
            }
            mx0 = fmaxf(mx0, __shfl_xor_sync(0xffffffffu, mx0, 1));
            mx0 = fmaxf(mx0, __shfl_xor_sync(0xffffffffu, mx0, 2));
            mx1 = fmaxf(mx1, __shfl_xor_sync(0xffffffffu, mx1, 1));
            mx1 = fmaxf(mx1, __shfl_xor_sync(0xffffffffu, mx1, 2));
            float mn0 = fmaxf(m0, mx0), mn1 = fmaxf(m1, mx1);
            float al0 = __expf(m0 - mn0), al1 = __expf(m1 - mn1);
            float ps0 = 0.f, ps1 = 0.f;
            #pragma unroll
            for (int j = 0; j < 8; j++) {
                sc[j][0] = __expf(sc[j][0] - mn0);
                sc[j][1] = __expf(sc[j][1] - mn0);
                sc[j][2] = __expf(sc[j][2] - mn1);
                sc[j][3] = __expf(sc[j][3] - mn1);
                ps0 += sc[j][0] + sc[j][1];
                ps1 += sc[j][2] + sc[j][3];
            }
            ps0 += __shfl_xor_sync(0xffffffffu, ps0, 1);
            ps0 += __shfl_xor_sync(0xffffffffu, ps0, 2);
            ps1 += __shfl_xor_sync(0xffffffffu, ps1, 1);
            ps1 += __shfl_xor_sync(0xffffffffu, ps1, 2);
            l0 = l0 * al0 + ps0;  m0 = mn0;
            l1 = l1 * al1 + ps1;  m1 = mn1;
            #pragma unroll
            for (int j = 0; j < 8; j++) {
                o[j][0] *= al0; o[j][1] *= al0;
                o[j][2] *= al1; o[j][3] *= al1;
            }

            const uint32_t vrow =
                Vh + (lane & 15) * AT_ROWB + ((lane >> 4) * 8) * 2;
            #pragma unroll
            for (int kk = 0; kk < 4; kk++) {
                uint32_t ph[4], pl[4];
                split_pack(sc[2*kk][0],   sc[2*kk][1],   ph[0], pl[0]);
                split_pack(sc[2*kk][2],   sc[2*kk][3],   ph[1], pl[1]);
                split_pack(sc[2*kk+1][0], sc[2*kk+1][1], ph[2], pl[2]);
                split_pack(sc[2*kk+1][2], sc[2*kk+1][3], ph[3], pl[3]);
                uint32_t rbase = vrow + 16 * kk * AT_ROWB;
                #pragma unroll
                for (int jp = 0; jp < 4; jp++) {
                    uint32_t bh4[4], bl4[4];
                    uint32_t ad = rbase + (16 * jp) * 2;
                    ldmx4t(bh4, ad);
                    ldmx4t(bl4, ad + AT_TILE);
                    float* o0 = o[2 * jp];
                    float* o1 = o[2 * jp + 1];
                    mma_bf16(o0[0], o0[1], o0[2], o0[3],
                             ph[0], ph[1], ph[2], ph[3], bh4[0], bh4[1]);
                    mma_bf16(o0[0], o0[1], o0[2], o0[3],
                             ph[0], ph[1], ph[2], ph[3], bl4[0], bl4[1]);
                    mma_bf16(o0[0], o0[1], o0[2], o0[3],
                             pl[0], pl[1], pl[2], pl[3], bh4[0], bh4[1]);
                    mma_bf16(o1[0], o1[1], o1[2], o1[3],
                             ph[0], ph[1], ph[2], ph[3], bh4[2], bh4[3]);
                    mma_bf16(o1[0], o1[1], o1[2], o1[3],
                             ph[0], ph[1], ph[2], ph[3], bl4[2], bl4[3]);
                    mma_bf16(o1[0], o1[1], o1[2], o1[3],
                             pl[0], pl[1], pl[2], pl[3], bh4[2], bh4[3]);
                }
            }
        }
        __syncthreads();
    }

    float i0 = 1.f / l0, i1 = 1.f / l1;
    size_t base0 = ((size_t)(b * T_ + r0)) * D_ + h * HD_;
    size_t base1 = ((size_t)(b * T_ + r0 + 8)) * D_ + h * HD_;
    #pragma unroll
    for (int j = 0; j < 8; j++) {
        int d = 8 * j + 2 * tg;
        uint32_t hi, lo;
        split_pack(o[j][0] * i0, o[j][1] * i0, hi, lo);
        *(uint32_t*)(g_ah + base0 + d) = hi;
        *(uint32_t*)(g_al + base0 + d) = lo;
        split_pack(o[j][2] * i1, o[j][3] * i1, hi, lo);
        *(uint32_t*)(g_ah + base1 + d) = hi;
        *(uint32_t*)(g_al + base1 + d) = lo;
    }
}

// ---------------------------------------------------------------------------
extern "C" void kernel_launch(void* const* d_in, const int* in_sizes, int n_in,
                              void* d_out, int out_size)
{
    const float* query = (const float*)d_in[0];
    const float* key   = (const float*)d_in[1];
    const float* value = (const float*)d_in[2];
    const float* Wq    = (const float*)d_in[3];
    const float* bq    = (const float*)d_in[4];
    const float* Wk    = (const float*)d_in[5];
    const float* bk    = (const float*)d_in[6];
    const float* Wv    = (const float*)d_in[7];
    const float* bv    = (const float*)d_in[8];
    const float* Wo    = (const float*)d_in[9];
    const float* bo    = (const float*)d_in[10];
    float* out = (float*)d_out;

    __nv_bfloat16 *xqh, *xql, *xkh, *xkl, *xvh, *xvl;
    __nv_bfloat16 *wqh, *wql, *wkh, *wkl, *wvh, *wvl, *woh, *wol;
    __nv_bfloat16 *qh, *ql, *kh, *kl, *vh, *vl, *ah, *al;
    cudaGetSymbolAddress((void**)&xqh, g_xqh); cudaGetSymbolAddress((void**)&xql, g_xql);
    cudaGetSymbolAddress((void**)&xkh, g_xkh); cudaGetSymbolAddress((void**)&xkl, g_xkl);
    cudaGetSymbolAddress((void**)&xvh, g_xvh); cudaGetSymbolAddress((void**)&xvl, g_xvl);
    cudaGetSymbolAddress((void**)&wqh, g_wqh); cudaGetSymbolAddress((void**)&wql, g_wql);
    cudaGetSymbolAddress((void**)&wkh, g_wkh); cudaGetSymbolAddress((void**)&wkl, g_wkl);
    cudaGetSymbolAddress((void**)&wvh, g_wvh); cudaGetSymbolAddress((void**)&wvl, g_wvl);
    cudaGetSymbolAddress((void**)&woh, g_woh); cudaGetSymbolAddress((void**)&wol, g_wol);
    cudaGetSymbolAddress((void**)&qh, g_qh);   cudaGetSymbolAddress((void**)&ql, g_ql);
    cudaGetSymbolAddress((void**)&kh, g_kh);   cudaGetSymbolAddress((void**)&kl, g_kl);
    cudaGetSymbolAddress((void**)&vh, g_vh);   cudaGetSymbolAddress((void**)&vl, g_vl);
    cudaGetSymbolAddress((void**)&ah, g_ah);   cudaGetSymbolAddress((void**)&al, g_al);

    cudaFuncSetAttribute(gemm_qkv, cudaFuncAttributeMaxDynamicSharedMemorySize, G_SMEM);
    cudaFuncSetAttribute(gemm_o,   cudaFuncAttributeMaxDynamicSharedMemorySize, G_SMEM);
    cudaFuncSetAttribute(attn_mma, cudaFuncAttributeMaxDynamicSharedMemorySize, AT_SMEM);

    // fused split: segs 0-2 inputs, 3-6 weights
    SplitArgs sa;
    sa.src[0] = query; sa.hi[0] = xqh; sa.lo[0] = xql;
    sa.src[1] = key;   sa.hi[1] = xkh; sa.lo[1] = xkl;
    sa.src[2] = value; sa.hi[2] = xvh; sa.lo[2] = xvl;
    sa.src[3] = Wq;    sa.hi[3] = wqh; sa.lo[3] = wql;
    sa.src[4] = Wk;    sa.hi[4] = wkh; sa.lo[4] = wkl;
    sa.src[5] = Wv;    sa.hi[5] = wvh; sa.lo[5] = wvl;
    sa.src[6] = Wo;    sa.hi[6] = woh; sa.lo[6] = wol;
    split_all<<<28672, 256>>>(sa);

    // fused QKV projections (R6 GEMM core, one launch)
    QKVArgs qa;
    qa.ah[0] = xqh; qa.al[0] = xql; qa.wh[0] = wqh; qa.wl[0] = wql;
    qa.bias[0] = bq; qa.ch[0] = qh; qa.cl[0] = ql;
    qa.ah[1] = xkh; qa.al[1] = xkl; qa.wh[1] = wkh; qa.wl[1] = wkl;
    qa.bias[1] = bk; qa.ch[1] = kh; qa.cl[1] = kl;
    qa.ah[2] = xvh; qa.al[2] = xvl; qa.wh[2] = wvh; qa.wl[2] = wvl;
    qa.bias[2] = bv; qa.ch[2] = vh; qa.cl[2] = vl;
    gemm_qkv<<<dim3(8, 64, 3), 256, G_SMEM>>>(qa);

    attn_mma<<<dim3(16, B_ * H_), 256, AT_SMEM>>>();

    gemm_o<<<dim3(8, 64, 1), 256, G_SMEM>>>(ah, al, woh, wol, bo, out);
}

// round 9
// speedup vs baseline: 1.2572x; 1.0751x over previous
#include <cuda_runtime.h>
#include <cuda_bf16.h>
#include <math.h>
#include <stdint.h>

#define B_   4
#define T_   2048
#define D_   1024
#define H_   16
#define HD_  64
#define M_   (B_ * T_)
#define SCALE_ 0.125f

// ---------------- scratch (device globals; no allocation allowed) ----------
__device__ __nv_bfloat16 g_xqh[(size_t)M_ * D_], g_xql[(size_t)M_ * D_];
__device__ __nv_bfloat16 g_xkh[(size_t)M_ * D_], g_xkl[(size_t)M_ * D_];
__device__ __nv_bfloat16 g_xvh[(size_t)M_ * D_], g_xvl[(size_t)M_ * D_];
__device__ __nv_bfloat16 g_wqh[(size_t)D_ * D_], g_wql[(size_t)D_ * D_];
__device__ __nv_bfloat16 g_wkh[(size_t)D_ * D_], g_wkl[(size_t)D_ * D_];
__device__ __nv_bfloat16 g_wvh[(size_t)D_ * D_], g_wvl[(size_t)D_ * D_];
__device__ __nv_bfloat16 g_woh[(size_t)D_ * D_], g_wol[(size_t)D_ * D_];
__device__ __nv_bfloat16 g_qh[(size_t)B_ * H_ * T_ * HD_], g_ql[(size_t)B_ * H_ * T_ * HD_];
__device__ __nv_bfloat16 g_kh[(size_t)B_ * H_ * T_ * HD_], g_kl[(size_t)B_ * H_ * T_ * HD_];
__device__ __nv_bfloat16 g_vh[(size_t)B_ * H_ * T_ * HD_], g_vl[(size_t)B_ * H_ * T_ * HD_];
__device__ __nv_bfloat16 g_ah[(size_t)M_ * D_], g_al[(size_t)M_ * D_];

// =========================== helpers ========================================
__device__ __forceinline__ uint32_t smem_u32(const void* p) {
    uint32_t a;
    asm("{ .reg .u64 t; cvta.to.shared.u64 t, %1; cvt.u32.u64 %0, t; }"
        : "=r"(a) : "l"(p));
    return a;
}

__device__ __forceinline__ void mma_bf16(
    float& c0, float& c1, float& c2, float& c3,
    uint32_t a0, uint32_t a1, uint32_t a2, uint32_t a3,
    uint32_t b0, uint32_t b1)
{
    asm volatile(
        "mma.sync.aligned.m16n8k16.row.col.f32.bf16.bf16.f32 "
        "{%0,%1,%2,%3}, {%4,%5,%6,%7}, {%8,%9}, {%0,%1,%2,%3};"
        : "+f"(c0), "+f"(c1), "+f"(c2), "+f"(c3)
        : "r"(a0), "r"(a1), "r"(a2), "r"(a3), "r"(b0), "r"(b1));
}

__device__ __forceinline__ void ldmx4(uint32_t* r, uint32_t a) {
    asm volatile(
        "ldmatrix.sync.aligned.m8n8.x4.shared.b16 {%0,%1,%2,%3}, [%4];"
        : "=r"(r[0]), "=r"(r[1]), "=r"(r[2]), "=r"(r[3]) : "r"(a));
}

__device__ __forceinline__ void ldmx4t(uint32_t* r, uint32_t a) {
    asm volatile(
        "ldmatrix.sync.aligned.m8n8.x4.trans.shared.b16 {%0,%1,%2,%3}, [%4];"
        : "=r"(r[0]), "=r"(r[1]), "=r"(r[2]), "=r"(r[3]) : "r"(a));
}

__device__ __forceinline__ void cp16(uint32_t dst, const void* src) {
    asm volatile("cp.async.cg.shared.global [%0], [%1], 16;"
                 :: "r"(dst), "l"(src));
}
#define CP_COMMIT() asm volatile("cp.async.commit_group;" ::: "memory")
#define CP_WAIT1()  asm volatile("cp.async.wait_group 1;" ::: "memory")
#define CP_WAIT0()  asm volatile("cp.async.wait_group 0;" ::: "memory")

__device__ __forceinline__ void split_pack(float x, float y,
                                           uint32_t& hi, uint32_t& lo) {
    __nv_bfloat162 h = __floats2bfloat162_rn(x, y);
    float2 f = __bfloat1622float2(h);
    __nv_bfloat162 l = __floats2bfloat162_rn(x - f.x, y - f.y);
    hi = *(uint32_t*)&h;
    lo = *(uint32_t*)&l;
}

// ---------------------------------------------------------------------------
// fused fp32 -> bf16 hi/lo split over all 7 tensors
// ---------------------------------------------------------------------------
struct SplitArgs {
    const float* src[7];
    __nv_bfloat16* hi[7];
    __nv_bfloat16* lo[7];
};

__global__ __launch_bounds__(256)
void split_all(SplitArgs a)
{
    int bx = blockIdx.x;
    int seg, base;
    if (bx < 24576) { seg = bx >> 13;            base = bx & 8191; }
    else            { seg = 3 + ((bx - 24576) >> 10); base = (bx - 24576) & 1023; }
    int i = base * 256 + threadIdx.x;
    float4 v = ((const float4*)a.src[seg])[i];
    uint32_t h0, h1, l0, l1;
    split_pack(v.x, v.y, h0, l0);
    split_pack(v.z, v.w, h1, l1);
    ((uint2*)a.hi[seg])[i] = make_uint2(h0, h1);
    ((uint2*)a.lo[seg])[i] = make_uint2(l0, l1);
}

// ---------------------------------------------------------------------------
// bf16-split GEMM v5: R6 compute shape (256 thr, warp tile 32x64, K-chunk 32)
// + 3-stage cp.async, ONE barrier per chunk, 64B swizzled rows (2 CTAs/SM).
//   C = (Ah+Al)[M,K] @ (Wh+Wl)[N,K]^T + bias  (3-term split)
// Swizzle: 16B-chunk c of row r stored at chunk (c ^ ((r>>1)&3)).
// ---------------------------------------------------------------------------
#define G_BUFB 8192                  // 128 rows x 64 B
#define G_STGB (4 * G_BUFB)          // Ah,Al,Wh,Wl = 32768 B
#define G_SMEM (3 * G_STGB)          // 98304 B  (2 CTAs/SM: 192 KB)

__device__ __forceinline__ uint32_t g_swz(uint32_t buf, int row, int kcol) {
    int c = kcol >> 3;                       // 16B chunk within row
    int cs = c ^ ((row >> 1) & 3);
    return buf + row * 64 + (cs << 4);
}

template<int LAYOUT>
__device__ __forceinline__ void gemm_core(
    const __nv_bfloat16* __restrict__ Ah_, const __nv_bfloat16* __restrict__ Al_,
    const __nv_bfloat16* __restrict__ Wh_, const __nv_bfloat16* __restrict__ Wl_,
    const float* __restrict__ bias,
    __nv_bfloat16* __restrict__ Chi, __nv_bfloat16* __restrict__ Clo,
    float* __restrict__ Cf, float scale)
{
    extern __shared__ __nv_bfloat16 smg[];
    const uint32_t smb = smem_u32(smg);

    const int tid = threadIdx.x;
    const int wid = tid >> 5;
    const int lane = tid & 31;
    const int group = lane >> 2;
    const int tg = lane & 3;
    const int wm = wid >> 1;
    const int wn = wid & 1;
    const int m0 = blockIdx.y * 128;
    const int n0 = blockIdx.x * 128;

    const int a_roff = ((lane >> 3) & 1) * 8 + (lane & 7);
    const int a_coff = (lane >> 4) * 8;
    const int b_roff = ((lane >> 4) & 1) * 8 + (lane & 7);
    const int b_coff = ((lane >> 3) & 1) * 8;

    // loader: 4 buffers x 128 rows x 64B = 2048 x 16B chunks; 8 per thread
    #define G_LOAD(CHUNK, STAGE) do {                                          \
        uint32_t dbase = smb + (STAGE) * G_STGB;                               \
        int k0 = (CHUNK) * 32;                                                 \
        _Pragma("unroll")                                                      \
        for (int i = 0; i < 8; i++) {                                          \
            int a = i >> 1;                                                    \
            int rem = ((i & 1) << 8) + tid;     /* 0..511 */                   \
            int row = rem >> 2, c = rem & 3;                                   \
            int cs = c ^ ((row >> 1) & 3);                                     \
            const __nv_bfloat16* sp = (a == 0) ? Ah_ : (a == 1) ? Al_          \
                                     : (a == 2) ? Wh_ : Wl_;                   \
            int grow = ((a < 2) ? m0 : n0) + row;                              \
            cp16(dbase + a * G_BUFB + row * 64 + cs * 16,                      \
                 sp + (size_t)grow * 1024 + k0 + c * 8);                       \
        }                                                                      \
    } while (0)

    float c[2][8][4];
    #pragma unroll
    for (int mt = 0; mt < 2; mt++)
        #pragma unroll
        for (int nt = 0; nt < 8; nt++)
            #pragma unroll
            for (int r = 0; r < 4; r++) c[mt][nt][r] = 0.f;

    G_LOAD(0, 0); CP_COMMIT();
    G_LOAD(1, 1); CP_COMMIT();

    for (int chunk = 0; chunk < 32; chunk++) {
        if (chunk == 31) { CP_WAIT0(); } else { CP_WAIT1(); }
        __syncthreads();
        // stage (chunk+2)%3 held chunk-1's data; all reads of it finished
        // before this barrier, so the refill below is race-free.
        if (chunk + 2 < 32) {
            G_LOAD(chunk + 2, (chunk + 2) % 3);
            CP_COMMIT();
        }

        const uint32_t sA = smb + (chunk % 3) * G_STGB;      // Ah
        const uint32_t sW = sA + 2 * G_BUFB;                 // Wh

        #pragma unroll
        for (int ks = 0; ks < 2; ks++) {
            const int koff = ks * 16;
            uint32_t ah[2][4], al[2][4];
            #pragma unroll
            for (int mt = 0; mt < 2; mt++) {
                uint32_t addr = g_swz(sA, wm * 32 + mt * 16 + a_roff, koff + a_coff);
                ldmx4(ah[mt], addr);
                ldmx4(al[mt], addr + G_BUFB);
            }
            #pragma unroll
            for (int jj = 0; jj < 4; jj++) {
                uint32_t addr = g_swz(sW, wn * 64 + jj * 16 + b_roff, koff + b_coff);
                uint32_t bh4[4], bl4[4];
                ldmx4(bh4, addr);
                ldmx4(bl4, addr + G_BUFB);
                #pragma unroll
                for (int half = 0; half < 2; half++) {
                    int nt = 2 * jj + half;
                    uint32_t b0h = bh4[2 * half], b1h = bh4[2 * half + 1];
                    uint32_t b0l = bl4[2 * half], b1l = bl4[2 * half + 1];
                    #pragma unroll
                    for (int mt = 0; mt < 2; mt++) {
                        float* cc = c[mt][nt];
                        mma_bf16(cc[0], cc[1], cc[2], cc[3],
                                 ah[mt][0], ah[mt][1], ah[mt][2], ah[mt][3], b0h, b1h);
                        mma_bf16(cc[0], cc[1], cc[2], cc[3],
                                 ah[mt][0], ah[mt][1], ah[mt][2], ah[mt][3], b0l, b1l);
                        mma_bf16(cc[0], cc[1], cc[2], cc[3],
                                 al[mt][0], al[mt][1], al[mt][2], al[mt][3], b0h, b1h);
                    }
                }
            }
        }
    }

    // epilogue
    #pragma unroll
    for (int mt = 0; mt < 2; mt++) {
        #pragma unroll
        for (int nt = 0; nt < 8; nt++) {
            int col = n0 + wn * 64 + nt * 8 + 2 * tg;
            float bx = bias[col], by = bias[col + 1];
            #pragma unroll
            for (int half = 0; half < 2; half++) {
                int row = m0 + wm * 32 + mt * 16 + group + half * 8;
                float vx = c[mt][nt][half * 2 + 0] + bx;
                float vy = c[mt][nt][half * 2 + 1] + by;
                if (LAYOUT == 1) {
                    *(float2*)(Cf + (size_t)row * 1024 + col) = make_float2(vx, vy);
                } else {
                    vx *= scale; vy *= scale;
                    int b = row >> 11;
                    int t = row & 2047;
                    int h = col >> 6;
                    int hd = col & 63;
                    size_t addr = ((size_t)(b * H_ + h) * T_ + t) * HD_ + hd;
                    uint32_t hi, lo;
                    split_pack(vx, vy, hi, lo);
                    *(uint32_t*)(Chi + addr) = hi;
                    *(uint32_t*)(Clo + addr) = lo;
                }
            }
        }
    }
}

struct QKVArgs {
    const __nv_bfloat16 *ah[3], *al[3], *wh[3], *wl[3];
    const float* bias[3];
    __nv_bfloat16 *ch[3], *cl[3];
};

__global__ __launch_bounds__(256)
void gemm_qkv(QKVArgs p)
{
    int z = blockIdx.z;
    gemm_core<0>(p.ah[z], p.al[z], p.wh[z], p.wl[z], p.bias[z],
                 p.ch[z], p.cl[z], nullptr, (z == 0) ? SCALE_ : 1.0f);
}

__global__ __launch_bounds__(256)
void gemm_o(const __nv_bfloat16* ah, const __nv_bfloat16* al,
            const __nv_bfloat16* wh, const __nv_bfloat16* wl,
            const float* bias, float* out)
{
    gemm_core<1>(ah, al, wh, wl, bias, nullptr, nullptr, out, 1.0f);
}

// ---------------------------------------------------------------------------
// Tensor-core flash attention (causal), ldmatrix K + trans-V — R6 proven.
// ---------------------------------------------------------------------------
#define AT_ROWB 144
#define AT_TILE (64 * AT_ROWB)
#define AT_STAGE (4 * AT_TILE)
#define AT_SMEM (2 * AT_STAGE)

__global__ __launch_bounds__(256, 1)
void attn_mma()
{
    extern __shared__ char smraw[];
    const uint32_t smb = smem_u32(smraw);
    const int tid = threadIdx.x;
    const int w = tid >> 5;
    const int lane = tid & 31;
    const int g = lane >> 2;
    const int tg = lane & 3;
    const int qt = 15 - blockIdx.x;
    const int bh = blockIdx.y;
    const int b = bh >> 4;
    const int h = bh & 15;

    const int r0 = qt * 128 + w * 16 + g;

    const int kb_roff = ((lane >> 4) & 1) * 8 + (lane & 7);
    const int kb_coff = ((lane >> 3) & 1) * 8;

    const __nv_bfloat16* qhp = g_qh + (size_t)bh * T_ * HD_;
    const __nv_bfloat16* qlp = g_ql + (size_t)bh * T_ * HD_;
    uint32_t qfh[4][4], qfl[4][4];
    #pragma unroll
    for (int ks = 0; ks < 4; ks++) {
        int d = ks * 16 + 2 * tg;
        size_t a0 = (size_t)r0 * HD_ + d;
        size_t a1 = (size_t)(r0 + 8) * HD_ + d;
        qfh[ks][0] = *(const uint32_t*)(qhp + a0);
        qfh[ks][1] = *(const uint32_t*)(qhp + a1);
        qfh[ks][2] = *(const uint32_t*)(qhp + a0 + 8);
        qfh[ks][3] = *(const uint32_t*)(qhp + a1 + 8);
        qfl[ks][0] = *(const uint32_t*)(qlp + a0);
        qfl[ks][1] = *(const uint32_t*)(qlp + a1);
        qfl[ks][2] = *(const uint32_t*)(qlp + a0 + 8);
        qfl[ks][3] = *(const uint32_t*)(qlp + a1 + 8);
    }

    const __nv_bfloat16* khp = g_kh + (size_t)bh * T_ * HD_;
    const __nv_bfloat16* klp = g_kl + (size_t)bh * T_ * HD_;
    const __nv_bfloat16* vhp = g_vh + (size_t)bh * T_ * HD_;
    const __nv_bfloat16* vlp = g_vl + (size_t)bh * T_ * HD_;

    float o[8][4];
    #pragma unroll
    for (int j = 0; j < 8; j++)
        #pragma unroll
        for (int r = 0; r < 4; r++) o[j][r] = 0.f;
    float m0 = -1e30f, m1 = -1e30f, l0 = 0.f, l1 = 0.f;

    const int nkt = 2 * qt + 2;
    const int last_kt = (qt * 128 + w * 16 + 15) >> 6;

    #define LOAD_TILE(KT, S) do {                                              \
        uint32_t dbase = smb + (S) * AT_STAGE;                                 \
        size_t toff = (size_t)(KT) * 64 * HD_;                                 \
        _Pragma("unroll")                                                      \
        for (int i = 0; i < 8; i++) {                                          \
            const __nv_bfloat16* sp = (i < 2) ? khp : (i < 4) ? klp            \
                                     : (i < 6) ? vhp : vlp;                    \
            int a = i >> 1;                                                    \
            int rem = ((i & 1) << 8) + tid;                                    \
            int row = rem >> 3, ch = rem & 7;                                  \
            cp16(dbase + a * AT_TILE + row * AT_ROWB + ch * 16,                \
                 sp + toff + (size_t)row * HD_ + ch * 8);                      \
        }                                                                      \
    } while (0)

    LOAD_TILE(0, 0);
    CP_COMMIT();

    for (int kt = 0; kt < nkt; kt++) {
        if (kt + 1 < nkt) {
            LOAD_TILE(kt + 1, (kt + 1) & 1);
            CP_COMMIT();
            CP_WAIT1();
        } else {
            CP_WAIT0();
        }
        __syncthreads();

        if (kt <= last_kt) {
            const uint32_t Kh = smb + (kt & 1) * AT_STAGE;
            const uint32_t Vh = Kh + 2 * AT_TILE;

            float sc[8][4];
            #pragma unroll
            for (int j = 0; j < 8; j++)
                #pragma unroll
                for (int r = 0; r < 4; r++) sc[j][r] = 0.f;

            #pragma unroll
            for (int ks = 0; ks < 4; ks++) {
                #pragma unroll
                for (int jj = 0; jj < 4; jj++) {
                    uint32_t addr = Kh + (16 * jj + kb_roff) * AT_ROWB
                                       + (16 * ks + kb_coff) * 2;
                    uint32_t kh4[4], kl4[4];
                    ldmx4(kh4, addr);
                    ldmx4(kl4, addr + AT_TILE);
                    #pragma unroll
                    for (int half = 0; half < 2; half++) {
                        float* cc = sc[2 * jj + half];
                        uint32_t b0h = kh4[2 * half], b1h = kh4[2 * half + 1];
                        uint32_t b0l = kl4[2 * half], b1l = kl4[2 * half + 1];
                        mma_bf16(cc[0], cc[1], cc[2], cc[3],
                                 qfh[ks][0], qfh[ks][1], qfh[ks][2], qfh[ks][3], b0h, b1h);
                        mma_bf16(cc[0], cc[1], cc[2], cc[3],
                                 qfh[ks][0], qfh[ks][1], qfh[ks][2], qfh[ks][3], b0l, b1l);
                        mma_bf16(cc[0], cc[1], cc[2], cc[3],
                                 qfl[ks][0], qfl[ks][1], qfl[ks][2], qfl[ks][3], b0h, b1h);
                    }
                }
            }

            if (kt == last_kt) {
                #pragma unroll
                for (int j = 0; j < 8; j++) {
                    int cgl = kt * 64 + 8 * j + 2 * tg;
                    if (cgl     > r0)     sc[j][0] = -1e30f;
                    if (cgl + 1 > r0)     sc[j][1] = -1e30f;
                    if (cgl     > r0 + 8) sc[j][2] = -1e30f;
                    if (cgl + 1 > r0 + 8) sc[j][3] = -1e30f;
                }
            }

            float mx0 = -1e30f, mx1 = -1e30f;
            #pragma unroll
            for (int j = 0; j < 8; j++) {
                mx0 = fmaxf(mx0, fmaxf(sc[j][0], sc[j][1]));
                mx1 = fmaxf(mx1, fmaxf(sc[j][2], sc[j][3]));
            }
            mx0 = fmaxf(mx0, __shfl_xor_sync(0xffffffffu, mx0, 1));
            mx0 = fmaxf(mx0, __shfl_xor_sync(0xffffffffu, mx0, 2));
            mx1 = fmaxf(mx1, __shfl_xor_sync(0xffffffffu, mx1, 1));
            mx1 = fmaxf(mx1, __shfl_xor_sync(0xffffffffu, mx1, 2));
            float mn0 = fmaxf(m0, mx0), mn1 = fmaxf(m1, mx1);
            float al0 = __expf(m0 - mn0), al1 = __expf(m1 - mn1);
            float ps0 = 0.f, ps1 = 0.f;
            #pragma unroll
            for (int j = 0; j < 8; j++) {
                sc[j][0] = __expf(sc[j][0] - mn0);
                sc[j][1] = __expf(sc[j][1] - mn0);
                sc[j][2] = __expf(sc[j][2] - mn1);
                sc[j][3] = __expf(sc[j][3] - mn1);
                ps0 += sc[j][0] + sc[j][1];
                ps1 += sc[j][2] + sc[j][3];
            }
            ps0 += __shfl_xor_sync(0xffffffffu, ps0, 1);
            ps0 += __shfl_xor_sync(0xffffffffu, ps0, 2);
            ps1 += __shfl_xor_sync(0xffffffffu, ps1, 1);
            ps1 += __shfl_xor_sync(0xffffffffu, ps1, 2);
            l0 = l0 * al0 + ps0;  m0 = mn0;
            l1 = l1 * al1 + ps1;  m1 = mn1;
            #pragma unroll
            for (int j = 0; j < 8; j++) {
                o[j][0] *= al0; o[j][1] *= al0;
                o[j][2] *= al1; o[j][3] *= al1;
            }

            const uint32_t vrow =
                Vh + (lane & 15) * AT_ROWB + ((lane >> 4) * 8) * 2;
            #pragma unroll
            for (int kk = 0; kk < 4; kk++) {
                uint32_t ph[4], pl[4];
                split_pack(sc[2*kk][0],   sc[2*kk][1],   ph[0], pl[0]);
                split_pack(sc[2*kk][2],   sc[2*kk][3],   ph[1], pl[1]);
                split_pack(sc[2*kk+1][0], sc[2*kk+1][1], ph[2], pl[2]);
                split_pack(sc[2*kk+1][2], sc[2*kk+1][3], ph[3], pl[3]);
                uint32_t rbase = vrow + 16 * kk * AT_ROWB;
                #pragma unroll
                for (int jp = 0; jp < 4; jp++) {
                    uint32_t bh4[4], bl4[4];
                    uint32_t ad = rbase + (16 * jp) * 2;
                    ldmx4t(bh4, ad);
                    ldmx4t(bl4, ad + AT_TILE);
                    float* o0 = o[2 * jp];
                    float* o1 = o[2 * jp + 1];
                    mma_bf16(o0[0], o0[1], o0[2], o0[3],
                             ph[0], ph[1], ph[2], ph[3], bh4[0], bh4[1]);
                    mma_bf16(o0[0], o0[1], o0[2], o0[3],
                             ph[0], ph[1], ph[2], ph[3], bl4[0], bl4[1]);
                    mma_bf16(o0[0], o0[1], o0[2], o0[3],
                             pl[0], pl[1], pl[2], pl[3], bh4[0], bh4[1]);
                    mma_bf16(o1[0], o1[1], o1[2], o1[3],
                             ph[0], ph[1], ph[2], ph[3], bh4[2], bh4[3]);
                    mma_bf16(o1[0], o1[1], o1[2], o1[3],
                             ph[0], ph[1], ph[2], ph[3], bl4[2], bl4[3]);
                    mma_bf16(o1[0], o1[1], o1[2], o1[3],
                             pl[0], pl[1], pl[2], pl[3], bh4[2], bh4[3]);
                }
            }
        }
        __syncthreads();
    }

    float i0 = 1.f / l0, i1 = 1.f / l1;
    size_t base0 = ((size_t)(b * T_ + r0)) * D_ + h * HD_;
    size_t base1 = ((size_t)(b * T_ + r0 + 8)) * D_ + h * HD_;
    #pragma unroll
    for (int j = 0; j < 8; j++) {
        int d = 8 * j + 2 * tg;
        uint32_t hi, lo;
        split_pack(o[j][0] * i0, o[j][1] * i0, hi, lo);
        *(uint32_t*)(g_ah + base0 + d) = hi;
        *(uint32_t*)(g_al + base0 + d) = lo;
        split_pack(o[j][2] * i1, o[j][3] * i1, hi, lo);
        *(uint32_t*)(g_ah + base1 + d) = hi;
        *(uint32_t*)(g_al + base1 + d) = lo;
    }
}

// ---------------------------------------------------------------------------
extern "C" void kernel_launch(void* const* d_in, const int* in_sizes, int n_in,
                              void* d_out, int out_size)
{
    const float* query = (const float*)d_in[0];
    const float* key   = (const float*)d_in[1];
    const float* value = (const float*)d_in[2];
    const float* Wq    = (const float*)d_in[3];
    const float* bq    = (const float*)d_in[4];
    const float* Wk    = (const float*)d_in[5];
    const float* bk    = (const float*)d_in[6];
    const float* Wv    = (const float*)d_in[7];
    const float* bv    = (const float*)d_in[8];
    const float* Wo    = (const float*)d_in[9];
    const float* bo    = (const float*)d_in[10];
    float* out = (float*)d_out;

    __nv_bfloat16 *xqh, *xql, *xkh, *xkl, *xvh, *xvl;
    __nv_bfloat16 *wqh, *wql, *wkh, *wkl, *wvh, *wvl, *woh, *wol;
    __nv_bfloat16 *qh, *ql, *kh, *kl, *vh, *vl, *ah, *al;
    cudaGetSymbolAddress((void**)&xqh, g_xqh); cudaGetSymbolAddress((void**)&xql, g_xql);
    cudaGetSymbolAddress((void**)&xkh, g_xkh); cudaGetSymbolAddress((void**)&xkl, g_xkl);
    cudaGetSymbolAddress((void**)&xvh, g_xvh); cudaGetSymbolAddress((void**)&xvl, g_xvl);
    cudaGetSymbolAddress((void**)&wqh, g_wqh); cudaGetSymbolAddress((void**)&wql, g_wql);
    cudaGetSymbolAddress((void**)&wkh, g_wkh); cudaGetSymbolAddress((void**)&wkl, g_wkl);
    cudaGetSymbolAddress((void**)&wvh, g_wvh); cudaGetSymbolAddress((void**)&wvl, g_wvl);
    cudaGetSymbolAddress((void**)&woh, g_woh); cudaGetSymbolAddress((void**)&wol, g_wol);
    cudaGetSymbolAddress((void**)&qh, g_qh);   cudaGetSymbolAddress((void**)&ql, g_ql);
    cudaGetSymbolAddress((void**)&kh, g_kh);   cudaGetSymbolAddress((void**)&kl, g_kl);
    cudaGetSymbolAddress((void**)&vh, g_vh);   cudaGetSymbolAddress((void**)&vl, g_vl);
    cudaGetSymbolAddress((void**)&ah, g_ah);   cudaGetSymbolAddress((void**)&al, g_al);

    cudaFuncSetAttribute(gemm_qkv, cudaFuncAttributeMaxDynamicSharedMemorySize, G_SMEM);
    cudaFuncSetAttribute(gemm_o,   cudaFuncAttributeMaxDynamicSharedMemorySize, G_SMEM);
    cudaFuncSetAttribute(attn_mma, cudaFuncAttributeMaxDynamicSharedMemorySize, AT_SMEM);

    SplitArgs sa;
    sa.src[0] = query; sa.hi[0] = xqh; sa.lo[0] = xql;
    sa.src[1] = key;   sa.hi[1] = xkh; sa.lo[1] = xkl;
    sa.src[2] = value; sa.hi[2] = xvh; sa.lo[2] = xvl;
    sa.src[3] = Wq;    sa.hi[3] = wqh; sa.lo[3] = wql;
    sa.src[4] = Wk;    sa.hi[4] = wkh; sa.lo[4] = wkl;
    sa.src[5] = Wv;    sa.hi[5] = wvh; sa.lo[5] = wvl;
    sa.src[6] = Wo;    sa.hi[6] = woh; sa.lo[6] = wol;
    split_all<<<28672, 256>>>(sa);

    QKVArgs qa;
    qa.ah[0] = xqh; qa.al[0] = xql; qa.wh[0] = wqh; qa.wl[0] = wql;
    qa.bias[0] = bq; qa.ch[0] = qh; qa.cl[0] = ql;
    qa.ah[1] = xkh; qa.al[1] = xkl; qa.wh[1] = wkh; qa.wl[1] = wkl;
    qa.bias[1] = bk; qa.ch[1] = kh; qa.cl[1] = kl;
    qa.ah[2] = xvh; qa.al[2] = xvl; qa.wh[2] = wvh; qa.wl[2] = wvl;
    qa.bias[2] = bv; qa.ch[2] = vh; qa.cl[2] = vl;
    gemm_qkv<<<dim3(8, 64, 3), 256, G_SMEM>>>(qa);

    attn_mma<<<dim3(16, B_ * H_), 256, AT_SMEM>>>();

    gemm_o<<<dim3(8, 64, 1), 256, G_SMEM>>>(ah, al, woh, wol, bo, out);
}